// round 3
// baseline (speedup 1.0000x reference)
#include <cuda_runtime.h>

#define EPS 1e-05f

// Device scratch (no allocations allowed anywhere in this file).
__device__ float g_tp;
__device__ float g_fp;
__device__ float g_fn;

__global__ void zero_scratch_kernel() {
    g_tp = 0.0f;
    g_fp = 0.0f;
    g_fn = 0.0f;
}

__global__ void __launch_bounds__(256)
reduce_kernel(const float4* __restrict__ probs4,
              const int4* __restrict__ lbls4,
              int n4) {
    float tp = 0.0f, fp = 0.0f, fn = 0.0f;

    int stride = gridDim.x * blockDim.x;
    for (int i = blockIdx.x * blockDim.x + threadIdx.x; i < n4; i += stride) {
        float4 p = probs4[i];
        int4   l = lbls4[i];

        {
            bool pp = p.x > 0.5f, pl = l.x == 1;
            tp += (pp & pl)  ? p.x        : 0.0f;
            fp += (pp & !pl) ? p.x        : 0.0f;
            fn += (!pp & pl) ? 1.0f - p.x : 0.0f;
        }
        {
            bool pp = p.y > 0.5f, pl = l.y == 1;
            tp += (pp & pl)  ? p.y        : 0.0f;
            fp += (pp & !pl) ? p.y        : 0.0f;
            fn += (!pp & pl) ? 1.0f - p.y : 0.0f;
        }
        {
            bool pp = p.z > 0.5f, pl = l.z == 1;
            tp += (pp & pl)  ? p.z        : 0.0f;
            fp += (pp & !pl) ? p.z        : 0.0f;
            fn += (!pp & pl) ? 1.0f - p.z : 0.0f;
        }
        {
            bool pp = p.w > 0.5f, pl = l.w == 1;
            tp += (pp & pl)  ? p.w        : 0.0f;
            fp += (pp & !pl) ? p.w        : 0.0f;
            fn += (!pp & pl) ? 1.0f - p.w : 0.0f;
        }
    }

    // Warp reduce
    #pragma unroll
    for (int off = 16; off > 0; off >>= 1) {
        tp += __shfl_down_sync(0xFFFFFFFFu, tp, off);
        fp += __shfl_down_sync(0xFFFFFFFFu, fp, off);
        fn += __shfl_down_sync(0xFFFFFFFFu, fn, off);
    }

    __shared__ float s_tp[8], s_fp[8], s_fn[8];
    int lane = threadIdx.x & 31;
    int wid  = threadIdx.x >> 5;
    if (lane == 0) { s_tp[wid] = tp; s_fp[wid] = fp; s_fn[wid] = fn; }
    __syncthreads();

    if (wid == 0) {
        tp = (lane < 8) ? s_tp[lane] : 0.0f;
        fp = (lane < 8) ? s_fp[lane] : 0.0f;
        fn = (lane < 8) ? s_fn[lane] : 0.0f;
        #pragma unroll
        for (int off = 4; off > 0; off >>= 1) {
            tp += __shfl_down_sync(0xFFFFFFFFu, tp, off);
            fp += __shfl_down_sync(0xFFFFFFFFu, fp, off);
            fn += __shfl_down_sync(0xFFFFFFFFu, fn, off);
        }
        if (lane == 0) {
            atomicAdd(&g_tp, tp);
            atomicAdd(&g_fp, fp);
            atomicAdd(&g_fn, fn);
        }
    }
}

__global__ void finalize_kernel(float* __restrict__ out) {
    float TP = g_tp, FP = g_fp, FN = g_fn;
    float precision = (TP + EPS) / (TP + FP + EPS);
    float recall    = (TP + EPS) / (TP + FN + EPS);
    float f1 = 2.0f * precision * recall / (precision + recall);
    out[0] = -f1;
}

extern "C" void kernel_launch(void* const* d_in, const int* in_sizes, int n_in,
                              void* d_out, int out_size) {
    const float* probs = (const float*)d_in[0];
    const int*   lbls  = (const int*)d_in[1];
    float* out = (float*)d_out;
    int n = in_sizes[0];
    int n4 = n >> 2;  // N = 16777216, divisible by 4

    zero_scratch_kernel<<<1, 1>>>();

    int threads = 256;
    int blocks = 1184;  // 148 SMs x 8 CTAs -> one full wave at 256 thr/CTA
    int max_blocks = (n4 + threads - 1) / threads;
    if (blocks > max_blocks) blocks = max_blocks;
    reduce_kernel<<<blocks, threads>>>((const float4*)probs, (const int4*)lbls, n4);

    finalize_kernel<<<1, 1>>>(out);
}

// round 4
// speedup vs baseline: 1.0679x; 1.0679x over previous
#include <cuda_runtime.h>

#define EPS 1e-05f

// Device scratch (zero-initialized in the module; the last block of every
// launch resets it back to zero, so every graph replay starts clean).
__device__ float g_tp = 0.0f;
__device__ float g_fp = 0.0f;
__device__ float g_fn = 0.0f;
__device__ unsigned int g_count = 0u;

__global__ void __launch_bounds__(256)
negf1_kernel(const float4* __restrict__ probs4,
             const int4* __restrict__ lbls4,
             int n4,
             float* __restrict__ out,
             int nblocks) {
    float tp = 0.0f, fp = 0.0f, fn = 0.0f;

    int stride = gridDim.x * blockDim.x;
    for (int i = blockIdx.x * blockDim.x + threadIdx.x; i < n4; i += stride) {
        float4 p = probs4[i];
        int4   l = lbls4[i];

        {
            bool pp = p.x > 0.5f, pl = l.x == 1;
            tp += (pp & pl)  ? p.x        : 0.0f;
            fp += (pp & !pl) ? p.x        : 0.0f;
            fn += (!pp & pl) ? 1.0f - p.x : 0.0f;
        }
        {
            bool pp = p.y > 0.5f, pl = l.y == 1;
            tp += (pp & pl)  ? p.y        : 0.0f;
            fp += (pp & !pl) ? p.y        : 0.0f;
            fn += (!pp & pl) ? 1.0f - p.y : 0.0f;
        }
        {
            bool pp = p.z > 0.5f, pl = l.z == 1;
            tp += (pp & pl)  ? p.z        : 0.0f;
            fp += (pp & !pl) ? p.z        : 0.0f;
            fn += (!pp & pl) ? 1.0f - p.z : 0.0f;
        }
        {
            bool pp = p.w > 0.5f, pl = l.w == 1;
            tp += (pp & pl)  ? p.w        : 0.0f;
            fp += (pp & !pl) ? p.w        : 0.0f;
            fn += (!pp & pl) ? 1.0f - p.w : 0.0f;
        }
    }

    // Warp reduce
    #pragma unroll
    for (int off = 16; off > 0; off >>= 1) {
        tp += __shfl_down_sync(0xFFFFFFFFu, tp, off);
        fp += __shfl_down_sync(0xFFFFFFFFu, fp, off);
        fn += __shfl_down_sync(0xFFFFFFFFu, fn, off);
    }

    __shared__ float s_tp[8], s_fp[8], s_fn[8];
    __shared__ bool  s_last;
    int lane = threadIdx.x & 31;
    int wid  = threadIdx.x >> 5;
    if (lane == 0) { s_tp[wid] = tp; s_fp[wid] = fp; s_fn[wid] = fn; }
    __syncthreads();

    if (wid == 0) {
        tp = (lane < 8) ? s_tp[lane] : 0.0f;
        fp = (lane < 8) ? s_fp[lane] : 0.0f;
        fn = (lane < 8) ? s_fn[lane] : 0.0f;
        #pragma unroll
        for (int off = 4; off > 0; off >>= 1) {
            tp += __shfl_down_sync(0xFFFFFFFFu, tp, off);
            fp += __shfl_down_sync(0xFFFFFFFFu, fp, off);
            fn += __shfl_down_sync(0xFFFFFFFFu, fn, off);
        }
        if (lane == 0) {
            atomicAdd(&g_tp, tp);
            atomicAdd(&g_fp, fp);
            atomicAdd(&g_fn, fn);
            // Make this block's contributions visible before taking a ticket.
            __threadfence();
            unsigned int ticket = atomicAdd(&g_count, 1u);
            s_last = (ticket == (unsigned int)(nblocks - 1));
        }
    }
    __syncthreads();

    // Last block to finish: finalize and reset scratch for the next replay.
    if (s_last && threadIdx.x == 0) {
        float TP = *(volatile float*)&g_tp;
        float FP = *(volatile float*)&g_fp;
        float FN = *(volatile float*)&g_fn;
        float precision = (TP + EPS) / (TP + FP + EPS);
        float recall    = (TP + EPS) / (TP + FN + EPS);
        float f1 = 2.0f * precision * recall / (precision + recall);
        out[0] = -f1;
        g_tp = 0.0f;
        g_fp = 0.0f;
        g_fn = 0.0f;
        g_count = 0u;
    }
}

extern "C" void kernel_launch(void* const* d_in, const int* in_sizes, int n_in,
                              void* d_out, int out_size) {
    const float* probs = (const float*)d_in[0];
    const int*   lbls  = (const int*)d_in[1];
    float* out = (float*)d_out;
    int n = in_sizes[0];
    int n4 = n >> 2;  // N = 16777216, divisible by 4

    int threads = 256;
    int blocks = 1184;  // 148 SMs x 8 CTAs -> one full wave at 256 thr/CTA
    int max_blocks = (n4 + threads - 1) / threads;
    if (blocks > max_blocks) blocks = max_blocks;

    negf1_kernel<<<blocks, threads>>>((const float4*)probs, (const int4*)lbls,
                                      n4, out, blocks);
}